// round 9
// baseline (speedup 1.0000x reference)
#include <cuda_runtime.h>
#include <cuda_bf16.h>
#include <cstdint>

#define BB 4
#define HH 16
#define LL 2048
#define DM 1024
#define DHEAD 64
#define NZ (BB * HH)
#define NJT (LL / 128)

// Scratch (__device__ globals; allocation-free rule)
__device__ float g_Q[(size_t)NZ * LL * DHEAD];
__device__ float g_K[(size_t)NZ * LL * DHEAD];
__device__ __nv_bfloat16 g_VT_H[(size_t)NZ * DHEAD * LL];  // [z][e][kv]
__device__ __nv_bfloat16 g_VT_L[(size_t)NZ * DHEAD * LL];
__device__ float g_ctx[(size_t)BB * LL * (HH * DHEAD)];
__device__ float2 g_stats[(size_t)NZ * NJT * LL];          // per (z, jtile, row): (max, sumexp)
__device__ float2 g_ML[(size_t)NZ * LL];                   // per (z, row): (M, 1/L)

// ===========================================================================
// mma.sync bf16 helpers (m16n8k16, row.col, f32 accum)
// ===========================================================================
__device__ __forceinline__ void mma_bf16(float* c,
                                         uint32_t a0, uint32_t a1, uint32_t a2, uint32_t a3,
                                         uint32_t b0, uint32_t b1)
{
    asm volatile(
        "mma.sync.aligned.m16n8k16.row.col.f32.bf16.bf16.f32 "
        "{%0,%1,%2,%3}, {%4,%5,%6,%7}, {%8,%9}, {%0,%1,%2,%3};"
        : "+f"(c[0]), "+f"(c[1]), "+f"(c[2]), "+f"(c[3])
        : "r"(a0), "r"(a1), "r"(a2), "r"(a3), "r"(b0), "r"(b1));
}
__device__ __forceinline__ void mma3(float* c,
                                     const uint32_t* ah, const uint32_t* al,
                                     const uint32_t* bh, const uint32_t* bl)
{
    mma_bf16(c, ah[0], ah[1], ah[2], ah[3], bh[0], bh[1]);
    mma_bf16(c, ah[0], ah[1], ah[2], ah[3], bl[0], bl[1]);
    mma_bf16(c, al[0], al[1], al[2], al[3], bh[0], bh[1]);
}
__device__ __forceinline__ void split_pair(float x, float y, uint32_t& h, uint32_t& l)
{
    __nv_bfloat16 hx = __float2bfloat16(x);
    __nv_bfloat16 hy = __float2bfloat16(y);
    __nv_bfloat162 hp = __halves2bfloat162(hx, hy);
    __nv_bfloat162 lp = __halves2bfloat162(__float2bfloat16(x - __bfloat162float(hx)),
                                           __float2bfloat16(y - __bfloat162float(hy)));
    h = *(uint32_t*)&hp;
    l = *(uint32_t*)&lp;
}
__device__ __forceinline__ void split_one(float x, __nv_bfloat16& h, __nv_bfloat16& l)
{
    h = __float2bfloat16(x);
    l = __float2bfloat16(x - __bfloat162float(h));
}

// ===========================================================================
// score_mma: raw S[z,i,j] = 0.125 * Q·K^T + per-(row, jtile) partial stats
// CTA 128x128, 512 threads / 16 warps (4x4), warp tile 32x32.
// grid=(16 j, 16 i, 64 z)
// ===========================================================================
__global__ __launch_bounds__(512) void score_mma(const float* __restrict__ Qp,
                                                 const float* __restrict__ Kp,
                                                 float* __restrict__ Sout,
                                                 float2* __restrict__ stats)
{
    extern __shared__ char smraw[];
    __nv_bfloat16* QH = (__nv_bfloat16*)smraw;        // [128][72]
    __nv_bfloat16* QL = QH + 128 * 72;
    __nv_bfloat16* KH = QL + 128 * 72;
    __nv_bfloat16* KL = KH + 128 * 72;
    float* Ssm = (float*)smraw;                       // epilogue reuse [128][132]

    const int tid = threadIdx.x, wid = tid >> 5, lane = tid & 31;
    const int wm = (wid >> 2) * 32, wn = (wid & 3) * 32;
    const int z = blockIdx.z, i0 = blockIdx.y * 128, j0 = blockIdx.x * 128;
    const float* Q = Qp + (size_t)z * LL * DHEAD;
    const float* K = Kp + (size_t)z * LL * DHEAD;

    #pragma unroll
    for (int t = 0; t < 4; t++) {
        int v = tid + t * 512;
        int r = v >> 4, c = (v & 15) * 4;
        float4 qv = *(const float4*)&Q[(size_t)(i0 + r) * DHEAD + c];
        uint32_t h0, l0, h1, l1;
        split_pair(qv.x, qv.y, h0, l0);
        split_pair(qv.z, qv.w, h1, l1);
        *(uint32_t*)&QH[r * 72 + c] = h0; *(uint32_t*)&QH[r * 72 + c + 2] = h1;
        *(uint32_t*)&QL[r * 72 + c] = l0; *(uint32_t*)&QL[r * 72 + c + 2] = l1;
        float4 kv = *(const float4*)&K[(size_t)(j0 + r) * DHEAD + c];
        split_pair(kv.x, kv.y, h0, l0);
        split_pair(kv.z, kv.w, h1, l1);
        *(uint32_t*)&KH[r * 72 + c] = h0; *(uint32_t*)&KH[r * 72 + c + 2] = h1;
        *(uint32_t*)&KL[r * 72 + c] = l0; *(uint32_t*)&KL[r * 72 + c + 2] = l1;
    }
    __syncthreads();

    float acc[2][4][4] = {};
    const int qr = lane >> 2, qc = (lane & 3) * 2;

    #pragma unroll
    for (int ks = 0; ks < 4; ks++) {
        const int k0 = ks * 16;
        uint32_t bh[4][2], bl[4][2];
        #pragma unroll
        for (int jn = 0; jn < 4; jn++) {
            int n = wn + jn * 8 + qr;
            bh[jn][0] = *(uint32_t*)&KH[n * 72 + k0 + qc];
            bh[jn][1] = *(uint32_t*)&KH[n * 72 + k0 + 8 + qc];
            bl[jn][0] = *(uint32_t*)&KL[n * 72 + k0 + qc];
            bl[jn][1] = *(uint32_t*)&KL[n * 72 + k0 + 8 + qc];
        }
        #pragma unroll
        for (int im = 0; im < 2; im++) {
            int m = wm + im * 16 + qr;
            uint32_t ah[4], al[4];
            ah[0] = *(uint32_t*)&QH[m * 72 + k0 + qc];
            ah[1] = *(uint32_t*)&QH[(m + 8) * 72 + k0 + qc];
            ah[2] = *(uint32_t*)&QH[m * 72 + k0 + 8 + qc];
            ah[3] = *(uint32_t*)&QH[(m + 8) * 72 + k0 + 8 + qc];
            al[0] = *(uint32_t*)&QL[m * 72 + k0 + qc];
            al[1] = *(uint32_t*)&QL[(m + 8) * 72 + k0 + qc];
            al[2] = *(uint32_t*)&QL[m * 72 + k0 + 8 + qc];
            al[3] = *(uint32_t*)&QL[(m + 8) * 72 + k0 + 8 + qc];
            #pragma unroll
            for (int jn = 0; jn < 4; jn++)
                mma3(acc[im][jn], ah, al, bh[jn], bl[jn]);
        }
    }
    __syncthreads();

    #pragma unroll
    for (int im = 0; im < 2; im++) {
        int row = wm + im * 16 + qr;
        #pragma unroll
        for (int jn = 0; jn < 4; jn++) {
            int col = wn + jn * 8 + qc;
            *(float2*)&Ssm[row * 132 + col] =
                make_float2(acc[im][jn][0] * 0.125f, acc[im][jn][1] * 0.125f);
            *(float2*)&Ssm[(row + 8) * 132 + col] =
                make_float2(acc[im][jn][2] * 0.125f, acc[im][jn][3] * 0.125f);
        }
    }
    __syncthreads();

    // Partial softmax stats: 4 threads per row, 32 cols each, shuffle-combined.
    {
        int row = tid >> 2, part = tid & 3;
        const float* rp = &Ssm[row * 132 + part * 32];
        float mx = rp[0];
        #pragma unroll
        for (int i = 1; i < 32; i++) mx = fmaxf(mx, rp[i]);
        mx = fmaxf(mx, __shfl_xor_sync(0xffffffffu, mx, 1));
        mx = fmaxf(mx, __shfl_xor_sync(0xffffffffu, mx, 2));
        float se = 0.0f;
        #pragma unroll
        for (int i = 0; i < 32; i++) se += __expf(rp[i] - mx);
        se += __shfl_xor_sync(0xffffffffu, se, 1);
        se += __shfl_xor_sync(0xffffffffu, se, 2);
        if (part == 0)
            stats[((size_t)z * NJT + blockIdx.x) * LL + i0 + row] = make_float2(mx, se);
    }

    float* S = Sout + (size_t)z * LL * LL;
    #pragma unroll
    for (int t = 0; t < 8; t++) {
        int v = tid + t * 512;
        int r = v >> 5, c = (v & 31) * 4;
        *(float4*)&S[(size_t)(i0 + r) * LL + j0 + c] = *(float4*)&Ssm[r * 132 + c];
    }
}

// ===========================================================================
// stats_combine: fold 16 j-tile partials into per-row (M, 1/L)
// grid = 512, block = 256 (one thread per (z,row))
// ===========================================================================
__global__ __launch_bounds__(256) void stats_combine(const float2* __restrict__ stats,
                                                     float2* __restrict__ ML)
{
    int idx = blockIdx.x * 256 + threadIdx.x;   // z*2048 + row
    int z = idx >> 11, row = idx & 2047;
    float M = -1e30f;
    float2 s[NJT];
    #pragma unroll
    for (int jt = 0; jt < NJT; jt++) {
        s[jt] = stats[((size_t)z * NJT + jt) * LL + row];
        M = fmaxf(M, s[jt].x);
    }
    float L = 0.0f;
    #pragma unroll
    for (int jt = 0; jt < NJT; jt++)
        L += s[jt].y * __expf(s[jt].x - M);
    ML[idx] = make_float2(M, 1.0f / L);
}

// ===========================================================================
// ctx_mma: normalize S in place -> attn, and ctx = attn @ V
// CTA 128x64, 512 threads / 16 warps (8x2), warp tile 16x32.
// grid=(16 i, 64 z)
// ===========================================================================
__global__ __launch_bounds__(512) void ctx_mma(float* __restrict__ Sm,
                                               const __nv_bfloat16* __restrict__ VTH,
                                               const __nv_bfloat16* __restrict__ VTL,
                                               const float2* __restrict__ ML,
                                               float* __restrict__ Ctx)
{
    extern __shared__ char smraw[];
    __nv_bfloat16* AH = (__nv_bfloat16*)smraw;     // [128][72]
    __nv_bfloat16* AL = AH + 128 * 72;
    __nv_bfloat16* TH = AL + 128 * 72;             // V^T chunk [64 e][72]
    __nv_bfloat16* TL = TH + 64 * 72;
    float2* MLs = (float2*)(TL + 64 * 72);         // [128]
    float* Cs = (float*)smraw;                     // epilogue reuse [128][68]

    const int tid = threadIdx.x, wid = tid >> 5, lane = tid & 31;
    const int wm = (wid >> 1) * 16, wn = (wid & 1) * 32;
    const int z = blockIdx.y, b = z >> 4, h = z & 15;
    const int i0 = blockIdx.x * 128;
    float* A = Sm + (size_t)z * LL * LL;

    if (tid < 128) MLs[tid] = ML[(size_t)z * LL + i0 + tid];
    __syncthreads();

    const int qr = lane >> 2, qc = (lane & 3) * 2;
    float acc[4][4] = {};

    for (int c = 0; c < 32; c++) {
        const int kv0 = c * 64;
        // S chunk 128x64: read, normalize, write back attn, split to planes
        #pragma unroll
        for (int t = 0; t < 4; t++) {
            int v = tid + t * 512;
            int r = v >> 4, cc = (v & 15) * 4;
            float* sp = &A[(size_t)(i0 + r) * LL + kv0 + cc];
            float4 sv = *(float4*)sp;
            float2 ml = MLs[r];
            float4 p;
            p.x = __expf(sv.x - ml.x) * ml.y;
            p.y = __expf(sv.y - ml.x) * ml.y;
            p.z = __expf(sv.z - ml.x) * ml.y;
            p.w = __expf(sv.w - ml.x) * ml.y;
            *(float4*)sp = p;
            uint32_t h0, l0, h1, l1;
            split_pair(p.x, p.y, h0, l0);
            split_pair(p.z, p.w, h1, l1);
            *(uint32_t*)&AH[r * 72 + cc] = h0; *(uint32_t*)&AH[r * 72 + cc + 2] = h1;
            *(uint32_t*)&AL[r * 72 + cc] = l0; *(uint32_t*)&AL[r * 72 + cc + 2] = l1;
        }
        // V^T chunk 64e x 64kv: vectorized loads of pre-split planes
        #pragma unroll
        for (int t = 0; t < 2; t++) {
            int v = tid + t * 512;
            int e = v >> 4, kp = (v & 15) * 4;
            *(uint2*)&TH[e * 72 + kp] =
                *(const uint2*)&VTH[((size_t)z * DHEAD + e) * LL + kv0 + kp];
            *(uint2*)&TL[e * 72 + kp] =
                *(const uint2*)&VTL[((size_t)z * DHEAD + e) * LL + kv0 + kp];
        }
        __syncthreads();

        #pragma unroll
        for (int ks = 0; ks < 4; ks++) {
            const int k0 = ks * 16;
            uint32_t bh[4][2], bl[4][2];
            #pragma unroll
            for (int jn = 0; jn < 4; jn++) {
                int n = wn + jn * 8 + qr;
                bh[jn][0] = *(uint32_t*)&TH[n * 72 + k0 + qc];
                bh[jn][1] = *(uint32_t*)&TH[n * 72 + k0 + 8 + qc];
                bl[jn][0] = *(uint32_t*)&TL[n * 72 + k0 + qc];
                bl[jn][1] = *(uint32_t*)&TL[n * 72 + k0 + 8 + qc];
            }
            int m = wm + qr;
            uint32_t ah[4], al[4];
            ah[0] = *(uint32_t*)&AH[m * 72 + k0 + qc];
            ah[1] = *(uint32_t*)&AH[(m + 8) * 72 + k0 + qc];
            ah[2] = *(uint32_t*)&AH[m * 72 + k0 + 8 + qc];
            ah[3] = *(uint32_t*)&AH[(m + 8) * 72 + k0 + 8 + qc];
            al[0] = *(uint32_t*)&AL[m * 72 + k0 + qc];
            al[1] = *(uint32_t*)&AL[(m + 8) * 72 + k0 + qc];
            al[2] = *(uint32_t*)&AL[m * 72 + k0 + 8 + qc];
            al[3] = *(uint32_t*)&AL[(m + 8) * 72 + k0 + 8 + qc];
            #pragma unroll
            for (int jn = 0; jn < 4; jn++)
                mma3(acc[jn], ah, al, bh[jn], bl[jn]);
        }
        __syncthreads();
    }

    // stage + coalesced write to ctx[b][q][h*64+e]
    {
        int row = wm + qr;
        #pragma unroll
        for (int jn = 0; jn < 4; jn++) {
            int col = wn + jn * 8 + qc;
            *(float2*)&Cs[row * 68 + col] = make_float2(acc[jn][0], acc[jn][1]);
            *(float2*)&Cs[(row + 8) * 68 + col] = make_float2(acc[jn][2], acc[jn][3]);
        }
    }
    __syncthreads();
    #pragma unroll
    for (int t = 0; t < 4; t++) {
        int v = tid + t * 512;
        int r = v >> 4, cc = (v & 15) * 4;
        *(float4*)&Ctx[((size_t)b * LL + i0 + r) * (HH * DHEAD) + h * DHEAD + cc] =
            *(float4*)&Cs[r * 68 + cc];
    }
}

// ===========================================================================
// proj_mma: Out[b,h,s,e] = sum_d X[b,s,d] W[h,d,e]
// mode 0: float row-major.  mode 1: split V^T planes [z][e][kv].
// ===========================================================================
__global__ __launch_bounds__(256) void proj_mma(const float* __restrict__ X,
                                                const float* __restrict__ W,
                                                float* __restrict__ OutF,
                                                __nv_bfloat16* __restrict__ OutH,
                                                __nv_bfloat16* __restrict__ OutL,
                                                int mode)
{
    extern __shared__ char smraw[];
    __nv_bfloat16* XH = (__nv_bfloat16*)smraw;     // [128][40]
    __nv_bfloat16* XL = XH + 128 * 40;
    __nv_bfloat16* TH = XL + 128 * 40;             // W^T [64 e][40]
    __nv_bfloat16* TL = TH + 64 * 40;
    float* Cs = (float*)smraw;                     // [128][68]

    const int tid = threadIdx.x, wid = tid >> 5, lane = tid & 31;
    const int wm = (wid >> 1) * 32, wn = (wid & 1) * 32;
    const int b = blockIdx.z, hh = blockIdx.y, i0 = blockIdx.x * 128;
    const int z = b * HH + hh;
    const float* A  = X + (size_t)b * LL * DM;
    const float* Bw = W + (size_t)hh * DM * DHEAD;

    const int qr = lane >> 2, qc = (lane & 3) * 2;
    float acc[2][4][4] = {};

    for (int c = 0; c < 32; c++) {
        const int k0g = c * 32;
        #pragma unroll
        for (int t = 0; t < 4; t++) {
            int v = tid + t * 256;
            int r = v >> 3, cc = (v & 7) * 4;
            float4 xv = *(const float4*)&A[(size_t)(i0 + r) * DM + k0g + cc];
            uint32_t h0, l0, h1, l1;
            split_pair(xv.x, xv.y, h0, l0);
            split_pair(xv.z, xv.w, h1, l1);
            *(uint32_t*)&XH[r * 40 + cc] = h0; *(uint32_t*)&XH[r * 40 + cc + 2] = h1;
            *(uint32_t*)&XL[r * 40 + cc] = l0; *(uint32_t*)&XL[r * 40 + cc + 2] = l1;
        }
        #pragma unroll
        for (int t = 0; t < 2; t++) {
            int v = tid + t * 256;
            int r = v >> 4, cc = (v & 15) * 4;
            float4 wv = *(const float4*)&Bw[(size_t)(k0g + r) * DHEAD + cc];
            float vals[4] = {wv.x, wv.y, wv.z, wv.w};
            #pragma unroll
            for (int jj = 0; jj < 4; jj++) {
                __nv_bfloat16 hh2, ll;
                split_one(vals[jj], hh2, ll);
                TH[(cc + jj) * 40 + r] = hh2;
                TL[(cc + jj) * 40 + r] = ll;
            }
        }
        __syncthreads();

        #pragma unroll
        for (int ks = 0; ks < 2; ks++) {
            const int k0 = ks * 16;
            uint32_t bh[4][2], bl[4][2];
            #pragma unroll
            for (int jn = 0; jn < 4; jn++) {
                int n = wn + jn * 8 + qr;
                bh[jn][0] = *(uint32_t*)&TH[n * 40 + k0 + qc];
                bh[jn][1] = *(uint32_t*)&TH[n * 40 + k0 + 8 + qc];
                bl[jn][0] = *(uint32_t*)&TL[n * 40 + k0 + qc];
                bl[jn][1] = *(uint32_t*)&TL[n * 40 + k0 + 8 + qc];
            }
            #pragma unroll
            for (int im = 0; im < 2; im++) {
                int m = wm + im * 16 + qr;
                uint32_t ah[4], al[4];
                ah[0] = *(uint32_t*)&XH[m * 40 + k0 + qc];
                ah[1] = *(uint32_t*)&XH[(m + 8) * 40 + k0 + qc];
                ah[2] = *(uint32_t*)&XH[m * 40 + k0 + 8 + qc];
                ah[3] = *(uint32_t*)&XH[(m + 8) * 40 + k0 + 8 + qc];
                al[0] = *(uint32_t*)&XL[m * 40 + k0 + qc];
                al[1] = *(uint32_t*)&XL[(m + 8) * 40 + k0 + qc];
                al[2] = *(uint32_t*)&XL[m * 40 + k0 + 8 + qc];
                al[3] = *(uint32_t*)&XL[(m + 8) * 40 + k0 + 8 + qc];
                #pragma unroll
                for (int jn = 0; jn < 4; jn++)
                    mma3(acc[im][jn], ah, al, bh[jn], bl[jn]);
            }
        }
        __syncthreads();
    }

    #pragma unroll
    for (int im = 0; im < 2; im++) {
        int row = wm + im * 16 + qr;
        #pragma unroll
        for (int jn = 0; jn < 4; jn++) {
            int col = wn + jn * 8 + qc;
            *(float2*)&Cs[row * 68 + col] = make_float2(acc[im][jn][0], acc[im][jn][1]);
            *(float2*)&Cs[(row + 8) * 68 + col] = make_float2(acc[im][jn][2], acc[im][jn][3]);
        }
    }
    __syncthreads();

    if (mode == 0) {
        float* Out = OutF + ((size_t)z * LL + i0) * DHEAD;
        #pragma unroll
        for (int t = 0; t < 8; t++) {
            int v = tid + t * 256;
            int r = v >> 4, cc = (v & 15) * 4;
            *(float4*)&Out[(size_t)r * DHEAD + cc] = *(float4*)&Cs[r * 68 + cc];
        }
    } else {
        #pragma unroll
        for (int t = 0; t < 32; t++) {
            int v = tid + t * 256;
            int e = v >> 7, row = v & 127;
            float val = Cs[row * 68 + e];
            __nv_bfloat16 hb, lb;
            split_one(val, hb, lb);
            size_t idx = ((size_t)z * DHEAD + e) * LL + i0 + row;
            OutH[idx] = hb;
            OutL[idx] = lb;
        }
    }
}

// ===========================================================================
// out_mma: Out(8192x1024) = Ctx(8192x1024) @ Wo(1024x1024)
// ===========================================================================
__global__ __launch_bounds__(256) void out_mma(const float* __restrict__ Ctx,
                                               const float* __restrict__ Wo,
                                               float* __restrict__ Out)
{
    extern __shared__ char smraw[];
    __nv_bfloat16* XH = (__nv_bfloat16*)smraw;     // [128][40]
    __nv_bfloat16* XL = XH + 128 * 40;
    __nv_bfloat16* TH = XL + 128 * 40;             // Wo^T [64 n][40]
    __nv_bfloat16* TL = TH + 64 * 40;
    float* Cs = (float*)smraw;

    const int tid = threadIdx.x, wid = tid >> 5, lane = tid & 31;
    const int wm = (wid >> 1) * 32, wn = (wid & 1) * 32;
    const int i0 = blockIdx.y * 128, j0 = blockIdx.x * 64;
    const int NN = HH * DHEAD;

    const int qr = lane >> 2, qc = (lane & 3) * 2;
    float acc[2][4][4] = {};

    for (int c = 0; c < 32; c++) {
        const int k0g = c * 32;
        #pragma unroll
        for (int t = 0; t < 4; t++) {
            int v = tid + t * 256;
            int r = v >> 3, cc = (v & 7) * 4;
            float4 xv = *(const float4*)&Ctx[(size_t)(i0 + r) * NN + k0g + cc];
            uint32_t h0, l0, h1, l1;
            split_pair(xv.x, xv.y, h0, l0);
            split_pair(xv.z, xv.w, h1, l1);
            *(uint32_t*)&XH[r * 40 + cc] = h0; *(uint32_t*)&XH[r * 40 + cc + 2] = h1;
            *(uint32_t*)&XL[r * 40 + cc] = l0; *(uint32_t*)&XL[r * 40 + cc + 2] = l1;
        }
        #pragma unroll
        for (int t = 0; t < 2; t++) {
            int v = tid + t * 256;
            int r = v >> 4, cc = (v & 15) * 4;
            float4 wv = *(const float4*)&Wo[(size_t)(k0g + r) * DM + j0 + cc];
            float vals[4] = {wv.x, wv.y, wv.z, wv.w};
            #pragma unroll
            for (int jj = 0; jj < 4; jj++) {
                __nv_bfloat16 hh, ll;
                split_one(vals[jj], hh, ll);
                TH[(cc + jj) * 40 + r] = hh;
                TL[(cc + jj) * 40 + r] = ll;
            }
        }
        __syncthreads();

        #pragma unroll
        for (int ks = 0; ks < 2; ks++) {
            const int k0 = ks * 16;
            uint32_t bh[4][2], bl[4][2];
            #pragma unroll
            for (int jn = 0; jn < 4; jn++) {
                int n = wn + jn * 8 + qr;
                bh[jn][0] = *(uint32_t*)&TH[n * 40 + k0 + qc];
                bh[jn][1] = *(uint32_t*)&TH[n * 40 + k0 + 8 + qc];
                bl[jn][0] = *(uint32_t*)&TL[n * 40 + k0 + qc];
                bl[jn][1] = *(uint32_t*)&TL[n * 40 + k0 + 8 + qc];
            }
            #pragma unroll
            for (int im = 0; im < 2; im++) {
                int m = wm + im * 16 + qr;
                uint32_t ah[4], al[4];
                ah[0] = *(uint32_t*)&XH[m * 40 + k0 + qc];
                ah[1] = *(uint32_t*)&XH[(m + 8) * 40 + k0 + qc];
                ah[2] = *(uint32_t*)&XH[m * 40 + k0 + 8 + qc];
                ah[3] = *(uint32_t*)&XH[(m + 8) * 40 + k0 + 8 + qc];
                al[0] = *(uint32_t*)&XL[m * 40 + k0 + qc];
                al[1] = *(uint32_t*)&XL[(m + 8) * 40 + k0 + qc];
                al[2] = *(uint32_t*)&XL[m * 40 + k0 + 8 + qc];
                al[3] = *(uint32_t*)&XL[(m + 8) * 40 + k0 + 8 + qc];
                #pragma unroll
                for (int jn = 0; jn < 4; jn++)
                    mma3(acc[im][jn], ah, al, bh[jn], bl[jn]);
            }
        }
        __syncthreads();
    }

    #pragma unroll
    for (int im = 0; im < 2; im++) {
        int row = wm + im * 16 + qr;
        #pragma unroll
        for (int jn = 0; jn < 4; jn++) {
            int col = wn + jn * 8 + qc;
            *(float2*)&Cs[row * 68 + col] = make_float2(acc[im][jn][0], acc[im][jn][1]);
            *(float2*)&Cs[(row + 8) * 68 + col] = make_float2(acc[im][jn][2], acc[im][jn][3]);
        }
    }
    __syncthreads();
    #pragma unroll
    for (int t = 0; t < 8; t++) {
        int v = tid + t * 256;
        int r = v >> 4, cc = (v & 15) * 4;
        *(float4*)&Out[(size_t)(i0 + r) * DM + j0 + cc] = *(float4*)&Cs[r * 68 + cc];
    }
}

// ===========================================================================
extern "C" void kernel_launch(void* const* d_in, const int* in_sizes, int n_in,
                              void* d_out, int out_size)
{
    const float* q  = (const float*)d_in[0];
    const float* k  = (const float*)d_in[1];
    const float* v  = (const float*)d_in[2];
    const float* wq = (const float*)d_in[3];
    const float* wk = (const float*)d_in[4];
    const float* wv = (const float*)d_in[5];
    const float* wo = (const float*)d_in[6];

    float* out = (float*)d_out;
    const size_t OUT_ELEMS = (size_t)BB * LL * DM;

    float *gQ, *gK, *gCtx;
    __nv_bfloat16 *gVTH, *gVTL;
    float2 *gStats, *gML;
    cudaGetSymbolAddress((void**)&gQ, g_Q);
    cudaGetSymbolAddress((void**)&gK, g_K);
    cudaGetSymbolAddress((void**)&gVTH, g_VT_H);
    cudaGetSymbolAddress((void**)&gVTL, g_VT_L);
    cudaGetSymbolAddress((void**)&gCtx, g_ctx);
    cudaGetSymbolAddress((void**)&gStats, g_stats);
    cudaGetSymbolAddress((void**)&gML, g_ML);

    float* attn = out + OUT_ELEMS;

    const int proj_smem = 34816;
    cudaFuncSetAttribute(proj_mma, cudaFuncAttributeMaxDynamicSharedMemorySize, proj_smem);
    proj_mma<<<dim3(LL / 128, HH, BB), dim3(256), proj_smem>>>(q, wq, gQ, nullptr, nullptr, 0);
    proj_mma<<<dim3(LL / 128, HH, BB), dim3(256), proj_smem>>>(k, wk, gK, nullptr, nullptr, 0);
    proj_mma<<<dim3(LL / 128, HH, BB), dim3(256), proj_smem>>>(v, wv, nullptr, gVTH, gVTL, 1);

    const int score_smem = 73728;
    cudaFuncSetAttribute(score_mma, cudaFuncAttributeMaxDynamicSharedMemorySize, score_smem);
    score_mma<<<dim3(LL / 128, LL / 128, NZ), dim3(512), score_smem>>>(gQ, gK, attn, gStats);

    stats_combine<<<dim3((NZ * LL) / 256), dim3(256)>>>(gStats, gML);

    const int ctx_smem = 56320;
    cudaFuncSetAttribute(ctx_mma, cudaFuncAttributeMaxDynamicSharedMemorySize, ctx_smem);
    ctx_mma<<<dim3(LL / 128, NZ), dim3(512), ctx_smem>>>(attn, gVTH, gVTL, gML, gCtx);

    const int out_smem = 34816;
    cudaFuncSetAttribute(out_mma, cudaFuncAttributeMaxDynamicSharedMemorySize, out_smem);
    out_mma<<<dim3(DM / 64, (BB * LL) / 128), dim3(256), out_smem>>>(gCtx, wo, out);
}

// round 10
// speedup vs baseline: 1.1090x; 1.1090x over previous
#include <cuda_runtime.h>
#include <cuda_bf16.h>
#include <cstdint>

#define BB 4
#define HH 16
#define LL 2048
#define DM 1024
#define DHEAD 64
#define NZ (BB * HH)

// Scratch (__device__ globals; allocation-free rule)
__device__ float g_Q[(size_t)NZ * LL * DHEAD];
__device__ float g_K[(size_t)NZ * LL * DHEAD];
__device__ __nv_bfloat16 g_VT_H[(size_t)NZ * DHEAD * LL];  // [z][e][kv]
__device__ __nv_bfloat16 g_VT_L[(size_t)NZ * DHEAD * LL];
__device__ float g_ctx[(size_t)BB * LL * (HH * DHEAD)];

// ===========================================================================
// mma.sync bf16 helpers (m16n8k16, row.col, f32 accum) + ldmatrix
// ===========================================================================
__device__ __forceinline__ void mma_bf16(float* c,
                                         uint32_t a0, uint32_t a1, uint32_t a2, uint32_t a3,
                                         uint32_t b0, uint32_t b1)
{
    asm volatile(
        "mma.sync.aligned.m16n8k16.row.col.f32.bf16.bf16.f32 "
        "{%0,%1,%2,%3}, {%4,%5,%6,%7}, {%8,%9}, {%0,%1,%2,%3};"
        : "+f"(c[0]), "+f"(c[1]), "+f"(c[2]), "+f"(c[3])
        : "r"(a0), "r"(a1), "r"(a2), "r"(a3), "r"(b0), "r"(b1));
}
__device__ __forceinline__ void mma3(float* c,
                                     const uint32_t* ah, const uint32_t* al,
                                     const uint32_t* bh, const uint32_t* bl)
{
    mma_bf16(c, ah[0], ah[1], ah[2], ah[3], bh[0], bh[1]);
    mma_bf16(c, ah[0], ah[1], ah[2], ah[3], bl[0], bl[1]);
    mma_bf16(c, al[0], al[1], al[2], al[3], bh[0], bh[1]);
}
__device__ __forceinline__ void ldsm_x4(uint32_t& r0, uint32_t& r1, uint32_t& r2, uint32_t& r3,
                                        uint32_t addr)
{
    asm volatile("ldmatrix.sync.aligned.m8n8.x4.shared.b16 {%0,%1,%2,%3}, [%4];"
                 : "=r"(r0), "=r"(r1), "=r"(r2), "=r"(r3) : "r"(addr));
}
__device__ __forceinline__ uint32_t smem_u32(const void* p)
{
    uint32_t a;
    asm("{ .reg .u64 t; cvta.to.shared.u64 t, %1; cvt.u32.u64 %0, t; }" : "=r"(a) : "l"(p));
    return a;
}
__device__ __forceinline__ void split_pair(float x, float y, uint32_t& h, uint32_t& l)
{
    __nv_bfloat16 hx = __float2bfloat16(x);
    __nv_bfloat16 hy = __float2bfloat16(y);
    __nv_bfloat162 hp = __halves2bfloat162(hx, hy);
    __nv_bfloat162 lp = __halves2bfloat162(__float2bfloat16(x - __bfloat162float(hx)),
                                           __float2bfloat16(y - __bfloat162float(hy)));
    h = *(uint32_t*)&hp;
    l = *(uint32_t*)&lp;
}
__device__ __forceinline__ void split_one(float x, __nv_bfloat16& h, __nv_bfloat16& l)
{
    h = __float2bfloat16(x);
    l = __float2bfloat16(x - __bfloat162float(h));
}

// ===========================================================================
// score_mma: S[z,i,j] = 0.125 * Q·K^T  (no stats — keep epilogue thin!)
// CTA 128x128, 512 threads / 16 warps (4x4), warp tile 32x32.
// Fragments via ldmatrix.x4. grid=(16 j, 16 i, 64 z)
// ===========================================================================
__global__ __launch_bounds__(512) void score_mma(const float* __restrict__ Qp,
                                                 const float* __restrict__ Kp,
                                                 float* __restrict__ Sout)
{
    extern __shared__ char smraw[];
    __nv_bfloat16* QH = (__nv_bfloat16*)smraw;        // [128][72]
    __nv_bfloat16* QL = QH + 128 * 72;
    __nv_bfloat16* KH = QL + 128 * 72;
    __nv_bfloat16* KL = KH + 128 * 72;
    float* Ssm = (float*)smraw;                       // epilogue reuse [128][132]

    const int tid = threadIdx.x, wid = tid >> 5, lane = tid & 31;
    const int wm = (wid >> 2) * 32, wn = (wid & 3) * 32;
    const int z = blockIdx.z, i0 = blockIdx.y * 128, j0 = blockIdx.x * 128;
    const float* Q = Qp + (size_t)z * LL * DHEAD;
    const float* K = Kp + (size_t)z * LL * DHEAD;

    #pragma unroll
    for (int t = 0; t < 4; t++) {
        int v = tid + t * 512;
        int r = v >> 4, c = (v & 15) * 4;
        float4 qv = *(const float4*)&Q[(size_t)(i0 + r) * DHEAD + c];
        uint32_t h0, l0, h1, l1;
        split_pair(qv.x, qv.y, h0, l0);
        split_pair(qv.z, qv.w, h1, l1);
        *(uint32_t*)&QH[r * 72 + c] = h0; *(uint32_t*)&QH[r * 72 + c + 2] = h1;
        *(uint32_t*)&QL[r * 72 + c] = l0; *(uint32_t*)&QL[r * 72 + c + 2] = l1;
        float4 kv = *(const float4*)&K[(size_t)(j0 + r) * DHEAD + c];
        split_pair(kv.x, kv.y, h0, l0);
        split_pair(kv.z, kv.w, h1, l1);
        *(uint32_t*)&KH[r * 72 + c] = h0; *(uint32_t*)&KH[r * 72 + c + 2] = h1;
        *(uint32_t*)&KL[r * 72 + c] = l0; *(uint32_t*)&KL[r * 72 + c + 2] = l1;
    }
    __syncthreads();

    const uint32_t qh_b = smem_u32(QH), ql_b = smem_u32(QL);
    const uint32_t kh_b = smem_u32(KH), kl_b = smem_u32(KL);

    float acc[2][4][4] = {};

    // per-lane ldmatrix address components (element offsets, *2 for bytes)
    const int a_row = lane & 15, a_koff = (lane >> 4) * 8;          // A x4
    const int b_row = ((lane >> 4) & 1) * 8 + (lane & 7);           // B x4 (2 n-tiles)
    const int b_koff = ((lane >> 3) & 1) * 8;

    #pragma unroll
    for (int ks = 0; ks < 4; ks++) {
        const int k0 = ks * 16;
        uint32_t bh[4][2], bl[4][2];
        #pragma unroll
        for (int jp = 0; jp < 2; jp++) {
            int n = wn + jp * 16;
            uint32_t boff = (uint32_t)((n + b_row) * 72 + k0 + b_koff) * 2;
            ldsm_x4(bh[jp*2][0], bh[jp*2][1], bh[jp*2+1][0], bh[jp*2+1][1], kh_b + boff);
            ldsm_x4(bl[jp*2][0], bl[jp*2][1], bl[jp*2+1][0], bl[jp*2+1][1], kl_b + boff);
        }
        #pragma unroll
        for (int im = 0; im < 2; im++) {
            int m = wm + im * 16;
            uint32_t aoff = (uint32_t)((m + a_row) * 72 + k0 + a_koff) * 2;
            uint32_t ah[4], al[4];
            ldsm_x4(ah[0], ah[1], ah[2], ah[3], qh_b + aoff);
            ldsm_x4(al[0], al[1], al[2], al[3], ql_b + aoff);
            #pragma unroll
            for (int jn = 0; jn < 4; jn++)
                mma3(acc[im][jn], ah, al, bh[jn], bl[jn]);
        }
    }
    __syncthreads();

    const int qr = lane >> 2, qc = (lane & 3) * 2;
    #pragma unroll
    for (int im = 0; im < 2; im++) {
        int row = wm + im * 16 + qr;
        #pragma unroll
        for (int jn = 0; jn < 4; jn++) {
            int col = wn + jn * 8 + qc;
            *(float2*)&Ssm[row * 132 + col] =
                make_float2(acc[im][jn][0] * 0.125f, acc[im][jn][1] * 0.125f);
            *(float2*)&Ssm[(row + 8) * 132 + col] =
                make_float2(acc[im][jn][2] * 0.125f, acc[im][jn][3] * 0.125f);
        }
    }
    __syncthreads();

    float* S = Sout + (size_t)z * LL * LL;
    #pragma unroll
    for (int t = 0; t < 8; t++) {
        int v = tid + t * 512;
        int r = v >> 5, c = (v & 31) * 4;
        *(float4*)&S[(size_t)(i0 + r) * LL + j0 + c] = *(float4*)&Ssm[r * 132 + c];
    }
}

// ===========================================================================
// ctx_mma: C[z] = attn[z](2048x2048) @ V[z](2048x64)
// CTA 128x64, 512 threads / 16 warps (8x2), warp tile 16x32. ldmatrix frags.
// grid=(16 i, 64 z)
// ===========================================================================
__global__ __launch_bounds__(512) void ctx_mma(const float* __restrict__ Sm,
                                               const __nv_bfloat16* __restrict__ VTH,
                                               const __nv_bfloat16* __restrict__ VTL,
                                               float* __restrict__ Ctx)
{
    extern __shared__ char smraw[];
    __nv_bfloat16* AH = (__nv_bfloat16*)smraw;     // [128][72]
    __nv_bfloat16* AL = AH + 128 * 72;
    __nv_bfloat16* TH = AL + 128 * 72;             // V^T chunk [64 e][72]
    __nv_bfloat16* TL = TH + 64 * 72;
    float* Cs = (float*)smraw;                     // epilogue reuse [128][68]

    const int tid = threadIdx.x, wid = tid >> 5, lane = tid & 31;
    const int wm = (wid >> 1) * 16, wn = (wid & 1) * 32;
    const int z = blockIdx.y, b = z >> 4, h = z & 15;
    const int i0 = blockIdx.x * 128;
    const float* A = Sm + (size_t)z * LL * LL;

    const uint32_t ah_b = smem_u32(AH), al_b = smem_u32(AL);
    const uint32_t th_b = smem_u32(TH), tl_b = smem_u32(TL);

    const int a_row = lane & 15, a_koff = (lane >> 4) * 8;
    const int b_row = ((lane >> 4) & 1) * 8 + (lane & 7);
    const int b_koff = ((lane >> 3) & 1) * 8;

    float acc[4][4] = {};

    for (int c = 0; c < 32; c++) {
        const int kv0 = c * 64;
        // attn tile 128x64 -> split planes
        #pragma unroll
        for (int t = 0; t < 4; t++) {
            int v = tid + t * 512;
            int r = v >> 4, cc = (v & 15) * 4;
            float4 av = *(const float4*)&A[(size_t)(i0 + r) * LL + kv0 + cc];
            uint32_t h0, l0, h1, l1;
            split_pair(av.x, av.y, h0, l0);
            split_pair(av.z, av.w, h1, l1);
            *(uint32_t*)&AH[r * 72 + cc] = h0; *(uint32_t*)&AH[r * 72 + cc + 2] = h1;
            *(uint32_t*)&AL[r * 72 + cc] = l0; *(uint32_t*)&AL[r * 72 + cc + 2] = l1;
        }
        // V^T chunk 64e x 64kv: vectorized loads of pre-split planes
        #pragma unroll
        for (int t = 0; t < 2; t++) {
            int v = tid + t * 512;
            int e = v >> 4, kp = (v & 15) * 4;
            *(uint2*)&TH[e * 72 + kp] =
                *(const uint2*)&VTH[((size_t)z * DHEAD + e) * LL + kv0 + kp];
            *(uint2*)&TL[e * 72 + kp] =
                *(const uint2*)&VTL[((size_t)z * DHEAD + e) * LL + kv0 + kp];
        }
        __syncthreads();

        #pragma unroll
        for (int ks = 0; ks < 4; ks++) {
            const int k0 = ks * 16;
            uint32_t bh[4][2], bl[4][2];
            #pragma unroll
            for (int jp = 0; jp < 2; jp++) {
                int n = wn + jp * 16;
                uint32_t boff = (uint32_t)((n + b_row) * 72 + k0 + b_koff) * 2;
                ldsm_x4(bh[jp*2][0], bh[jp*2][1], bh[jp*2+1][0], bh[jp*2+1][1], th_b + boff);
                ldsm_x4(bl[jp*2][0], bl[jp*2][1], bl[jp*2+1][0], bl[jp*2+1][1], tl_b + boff);
            }
            uint32_t aoff = (uint32_t)((wm + a_row) * 72 + k0 + a_koff) * 2;
            uint32_t ah[4], al[4];
            ldsm_x4(ah[0], ah[1], ah[2], ah[3], ah_b + aoff);
            ldsm_x4(al[0], al[1], al[2], al[3], al_b + aoff);
            #pragma unroll
            for (int jn = 0; jn < 4; jn++)
                mma3(acc[jn], ah, al, bh[jn], bl[jn]);
        }
        __syncthreads();
    }

    // stage + coalesced write to ctx[b][q][h*64+e]
    const int qr = lane >> 2, qc = (lane & 3) * 2;
    {
        int row = wm + qr;
        #pragma unroll
        for (int jn = 0; jn < 4; jn++) {
            int col = wn + jn * 8 + qc;
            *(float2*)&Cs[row * 68 + col] = make_float2(acc[jn][0], acc[jn][1]);
            *(float2*)&Cs[(row + 8) * 68 + col] = make_float2(acc[jn][2], acc[jn][3]);
        }
    }
    __syncthreads();
    #pragma unroll
    for (int t = 0; t < 4; t++) {
        int v = tid + t * 512;
        int r = v >> 4, cc = (v & 15) * 4;
        *(float4*)&Ctx[((size_t)b * LL + i0 + r) * (HH * DHEAD) + h * DHEAD + cc] =
            *(float4*)&Cs[r * 68 + cc];
    }
}

// ===========================================================================
// proj_mma: Out[b,h,s,e] = sum_d X[b,s,d] W[h,d,e]   (R7-exact)
// mode 0: float row-major.  mode 1: split V^T planes [z][e][kv].
// ===========================================================================
__global__ __launch_bounds__(256) void proj_mma(const float* __restrict__ X,
                                                const float* __restrict__ W,
                                                float* __restrict__ OutF,
                                                __nv_bfloat16* __restrict__ OutH,
                                                __nv_bfloat16* __restrict__ OutL,
                                                int mode)
{
    extern __shared__ char smraw[];
    __nv_bfloat16* XH = (__nv_bfloat16*)smraw;     // [128][40]
    __nv_bfloat16* XL = XH + 128 * 40;
    __nv_bfloat16* TH = XL + 128 * 40;             // W^T [64 e][40]
    __nv_bfloat16* TL = TH + 64 * 40;
    float* Cs = (float*)smraw;                     // [128][68]

    const int tid = threadIdx.x, wid = tid >> 5, lane = tid & 31;
    const int wm = (wid >> 1) * 32, wn = (wid & 1) * 32;
    const int b = blockIdx.z, hh = blockIdx.y, i0 = blockIdx.x * 128;
    const int z = b * HH + hh;
    const float* A  = X + (size_t)b * LL * DM;
    const float* Bw = W + (size_t)hh * DM * DHEAD;

    const int qr = lane >> 2, qc = (lane & 3) * 2;
    float acc[2][4][4] = {};

    for (int c = 0; c < 32; c++) {
        const int k0g = c * 32;
        #pragma unroll
        for (int t = 0; t < 4; t++) {
            int v = tid + t * 256;
            int r = v >> 3, cc = (v & 7) * 4;
            float4 xv = *(const float4*)&A[(size_t)(i0 + r) * DM + k0g + cc];
            uint32_t h0, l0, h1, l1;
            split_pair(xv.x, xv.y, h0, l0);
            split_pair(xv.z, xv.w, h1, l1);
            *(uint32_t*)&XH[r * 40 + cc] = h0; *(uint32_t*)&XH[r * 40 + cc + 2] = h1;
            *(uint32_t*)&XL[r * 40 + cc] = l0; *(uint32_t*)&XL[r * 40 + cc + 2] = l1;
        }
        #pragma unroll
        for (int t = 0; t < 2; t++) {
            int v = tid + t * 256;
            int r = v >> 4, cc = (v & 15) * 4;
            float4 wv = *(const float4*)&Bw[(size_t)(k0g + r) * DHEAD + cc];
            float vals[4] = {wv.x, wv.y, wv.z, wv.w};
            #pragma unroll
            for (int jj = 0; jj < 4; jj++) {
                __nv_bfloat16 hh2, ll;
                split_one(vals[jj], hh2, ll);
                TH[(cc + jj) * 40 + r] = hh2;
                TL[(cc + jj) * 40 + r] = ll;
            }
        }
        __syncthreads();

        #pragma unroll
        for (int ks = 0; ks < 2; ks++) {
            const int k0 = ks * 16;
            uint32_t bh[4][2], bl[4][2];
            #pragma unroll
            for (int jn = 0; jn < 4; jn++) {
                int n = wn + jn * 8 + qr;
                bh[jn][0] = *(uint32_t*)&TH[n * 40 + k0 + qc];
                bh[jn][1] = *(uint32_t*)&TH[n * 40 + k0 + 8 + qc];
                bl[jn][0] = *(uint32_t*)&TL[n * 40 + k0 + qc];
                bl[jn][1] = *(uint32_t*)&TL[n * 40 + k0 + 8 + qc];
            }
            #pragma unroll
            for (int im = 0; im < 2; im++) {
                int m = wm + im * 16 + qr;
                uint32_t ah[4], al[4];
                ah[0] = *(uint32_t*)&XH[m * 40 + k0 + qc];
                ah[1] = *(uint32_t*)&XH[(m + 8) * 40 + k0 + qc];
                ah[2] = *(uint32_t*)&XH[m * 40 + k0 + 8 + qc];
                ah[3] = *(uint32_t*)&XH[(m + 8) * 40 + k0 + 8 + qc];
                al[0] = *(uint32_t*)&XL[m * 40 + k0 + qc];
                al[1] = *(uint32_t*)&XL[(m + 8) * 40 + k0 + qc];
                al[2] = *(uint32_t*)&XL[m * 40 + k0 + 8 + qc];
                al[3] = *(uint32_t*)&XL[(m + 8) * 40 + k0 + 8 + qc];
                #pragma unroll
                for (int jn = 0; jn < 4; jn++)
                    mma3(acc[im][jn], ah, al, bh[jn], bl[jn]);
            }
        }
        __syncthreads();
    }

    #pragma unroll
    for (int im = 0; im < 2; im++) {
        int row = wm + im * 16 + qr;
        #pragma unroll
        for (int jn = 0; jn < 4; jn++) {
            int col = wn + jn * 8 + qc;
            *(float2*)&Cs[row * 68 + col] = make_float2(acc[im][jn][0], acc[im][jn][1]);
            *(float2*)&Cs[(row + 8) * 68 + col] = make_float2(acc[im][jn][2], acc[im][jn][3]);
        }
    }
    __syncthreads();

    if (mode == 0) {
        float* Out = OutF + ((size_t)z * LL + i0) * DHEAD;
        #pragma unroll
        for (int t = 0; t < 8; t++) {
            int v = tid + t * 256;
            int r = v >> 4, cc = (v & 15) * 4;
            *(float4*)&Out[(size_t)r * DHEAD + cc] = *(float4*)&Cs[r * 68 + cc];
        }
    } else {
        #pragma unroll
        for (int t = 0; t < 32; t++) {
            int v = tid + t * 256;
            int e = v >> 7, row = v & 127;
            float val = Cs[row * 68 + e];
            __nv_bfloat16 hb, lb;
            split_one(val, hb, lb);
            size_t idx = ((size_t)z * DHEAD + e) * LL + i0 + row;
            OutH[idx] = hb;
            OutL[idx] = lb;
        }
    }
}

// ===========================================================================
// out_mma: Out(8192x1024) = Ctx(8192x1024) @ Wo(1024x1024)   (R7-exact)
// ===========================================================================
__global__ __launch_bounds__(256) void out_mma(const float* __restrict__ Ctx,
                                               const float* __restrict__ Wo,
                                               float* __restrict__ Out)
{
    extern __shared__ char smraw[];
    __nv_bfloat16* XH = (__nv_bfloat16*)smraw;     // [128][40]
    __nv_bfloat16* XL = XH + 128 * 40;
    __nv_bfloat16* TH = XL + 128 * 40;             // Wo^T [64 n][40]
    __nv_bfloat16* TL = TH + 64 * 40;
    float* Cs = (float*)smraw;

    const int tid = threadIdx.x, wid = tid >> 5, lane = tid & 31;
    const int wm = (wid >> 1) * 32, wn = (wid & 1) * 32;
    const int i0 = blockIdx.y * 128, j0 = blockIdx.x * 64;
    const int NN = HH * DHEAD;

    const int qr = lane >> 2, qc = (lane & 3) * 2;
    float acc[2][4][4] = {};

    for (int c = 0; c < 32; c++) {
        const int k0g = c * 32;
        #pragma unroll
        for (int t = 0; t < 4; t++) {
            int v = tid + t * 256;
            int r = v >> 3, cc = (v & 7) * 4;
            float4 xv = *(const float4*)&Ctx[(size_t)(i0 + r) * NN + k0g + cc];
            uint32_t h0, l0, h1, l1;
            split_pair(xv.x, xv.y, h0, l0);
            split_pair(xv.z, xv.w, h1, l1);
            *(uint32_t*)&XH[r * 40 + cc] = h0; *(uint32_t*)&XH[r * 40 + cc + 2] = h1;
            *(uint32_t*)&XL[r * 40 + cc] = l0; *(uint32_t*)&XL[r * 40 + cc + 2] = l1;
        }
        #pragma unroll
        for (int t = 0; t < 2; t++) {
            int v = tid + t * 256;
            int r = v >> 4, cc = (v & 15) * 4;
            float4 wv = *(const float4*)&Wo[(size_t)(k0g + r) * DM + j0 + cc];
            float vals[4] = {wv.x, wv.y, wv.z, wv.w};
            #pragma unroll
            for (int jj = 0; jj < 4; jj++) {
                __nv_bfloat16 hh, ll;
                split_one(vals[jj], hh, ll);
                TH[(cc + jj) * 40 + r] = hh;
                TL[(cc + jj) * 40 + r] = ll;
            }
        }
        __syncthreads();

        #pragma unroll
        for (int ks = 0; ks < 2; ks++) {
            const int k0 = ks * 16;
            uint32_t bh[4][2], bl[4][2];
            #pragma unroll
            for (int jn = 0; jn < 4; jn++) {
                int n = wn + jn * 8 + qr;
                bh[jn][0] = *(uint32_t*)&TH[n * 40 + k0 + qc];
                bh[jn][1] = *(uint32_t*)&TH[n * 40 + k0 + 8 + qc];
                bl[jn][0] = *(uint32_t*)&TL[n * 40 + k0 + qc];
                bl[jn][1] = *(uint32_t*)&TL[n * 40 + k0 + 8 + qc];
            }
            #pragma unroll
            for (int im = 0; im < 2; im++) {
                int m = wm + im * 16 + qr;
                uint32_t ah[4], al[4];
                ah[0] = *(uint32_t*)&XH[m * 40 + k0 + qc];
                ah[1] = *(uint32_t*)&XH[(m + 8) * 40 + k0 + qc];
                ah[2] = *(uint32_t*)&XH[m * 40 + k0 + 8 + qc];
                ah[3] = *(uint32_t*)&XH[(m + 8) * 40 + k0 + 8 + qc];
                al[0] = *(uint32_t*)&XL[m * 40 + k0 + qc];
                al[1] = *(uint32_t*)&XL[(m + 8) * 40 + k0 + qc];
                al[2] = *(uint32_t*)&XL[m * 40 + k0 + 8 + qc];
                al[3] = *(uint32_t*)&XL[(m + 8) * 40 + k0 + 8 + qc];
                #pragma unroll
                for (int jn = 0; jn < 4; jn++)
                    mma3(acc[im][jn], ah, al, bh[jn], bl[jn]);
            }
        }
        __syncthreads();
    }

    #pragma unroll
    for (int im = 0; im < 2; im++) {
        int row = wm + im * 16 + qr;
        #pragma unroll
        for (int jn = 0; jn < 4; jn++) {
            int col = wn + jn * 8 + qc;
            *(float2*)&Cs[row * 68 + col] = make_float2(acc[im][jn][0], acc[im][jn][1]);
            *(float2*)&Cs[(row + 8) * 68 + col] = make_float2(acc[im][jn][2], acc[im][jn][3]);
        }
    }
    __syncthreads();
    #pragma unroll
    for (int t = 0; t < 8; t++) {
        int v = tid + t * 256;
        int r = v >> 4, cc = (v & 15) * 4;
        *(float4*)&Out[(size_t)(i0 + r) * DM + j0 + cc] = *(float4*)&Cs[r * 68 + cc];
    }
}

// ===========================================================================
// Row softmax, 2048 elems, in place. grid=(131072), block=256   (R7-exact)
// ===========================================================================
__global__ __launch_bounds__(256) void softmax_kernel(float* __restrict__ S)
{
    float4* p4 = (float4*)(S + (size_t)blockIdx.x * LL);
    const int tid = threadIdx.x;
    const int warp = tid >> 5, lane = tid & 31;
    __shared__ float red[8];

    float4 v0 = p4[tid], v1 = p4[tid + 256];
    float m = fmaxf(fmaxf(fmaxf(v0.x, v0.y), fmaxf(v0.z, v0.w)),
                    fmaxf(fmaxf(v1.x, v1.y), fmaxf(v1.z, v1.w)));
    #pragma unroll
    for (int o = 16; o > 0; o >>= 1) m = fmaxf(m, __shfl_xor_sync(0xffffffffu, m, o));
    if (lane == 0) red[warp] = m;
    __syncthreads();
    if (tid < 8) {
        float t = red[tid];
        #pragma unroll
        for (int o = 4; o > 0; o >>= 1) t = fmaxf(t, __shfl_xor_sync(0xffu, t, o));
        if (tid == 0) red[0] = t;
    }
    __syncthreads();
    m = red[0];
    __syncthreads();

    v0.x = __expf(v0.x - m); v0.y = __expf(v0.y - m);
    v0.z = __expf(v0.z - m); v0.w = __expf(v0.w - m);
    v1.x = __expf(v1.x - m); v1.y = __expf(v1.y - m);
    v1.z = __expf(v1.z - m); v1.w = __expf(v1.w - m);
    float s = v0.x + v0.y + v0.z + v0.w + v1.x + v1.y + v1.z + v1.w;
    #pragma unroll
    for (int o = 16; o > 0; o >>= 1) s += __shfl_xor_sync(0xffffffffu, s, o);
    if (lane == 0) red[warp] = s;
    __syncthreads();
    if (tid < 8) {
        float t = red[tid];
        #pragma unroll
        for (int o = 4; o > 0; o >>= 1) t += __shfl_xor_sync(0xffu, t, o);
        if (tid == 0) red[0] = t;
    }
    __syncthreads();
    float inv = 1.0f / red[0];

    v0.x *= inv; v0.y *= inv; v0.z *= inv; v0.w *= inv;
    v1.x *= inv; v1.y *= inv; v1.z *= inv; v1.w *= inv;
    p4[tid] = v0; p4[tid + 256] = v1;
}

// ===========================================================================
extern "C" void kernel_launch(void* const* d_in, const int* in_sizes, int n_in,
                              void* d_out, int out_size)
{
    const float* q  = (const float*)d_in[0];
    const float* k  = (const float*)d_in[1];
    const float* v  = (const float*)d_in[2];
    const float* wq = (const float*)d_in[3];
    const float* wk = (const float*)d_in[4];
    const float* wv = (const float*)d_in[5];
    const float* wo = (const float*)d_in[6];

    float* out = (float*)d_out;
    const size_t OUT_ELEMS = (size_t)BB * LL * DM;

    float *gQ, *gK, *gCtx;
    __nv_bfloat16 *gVTH, *gVTL;
    cudaGetSymbolAddress((void**)&gQ, g_Q);
    cudaGetSymbolAddress((void**)&gK, g_K);
    cudaGetSymbolAddress((void**)&gVTH, g_VT_H);
    cudaGetSymbolAddress((void**)&gVTL, g_VT_L);
    cudaGetSymbolAddress((void**)&gCtx, g_ctx);

    float* attn = out + OUT_ELEMS;

    const int proj_smem = 34816;
    cudaFuncSetAttribute(proj_mma, cudaFuncAttributeMaxDynamicSharedMemorySize, proj_smem);
    proj_mma<<<dim3(LL / 128, HH, BB), dim3(256), proj_smem>>>(q, wq, gQ, nullptr, nullptr, 0);
    proj_mma<<<dim3(LL / 128, HH, BB), dim3(256), proj_smem>>>(k, wk, gK, nullptr, nullptr, 0);
    proj_mma<<<dim3(LL / 128, HH, BB), dim3(256), proj_smem>>>(v, wv, nullptr, gVTH, gVTL, 1);

    const int score_smem = 73728;
    cudaFuncSetAttribute(score_mma, cudaFuncAttributeMaxDynamicSharedMemorySize, score_smem);
    score_mma<<<dim3(LL / 128, LL / 128, NZ), dim3(512), score_smem>>>(gQ, gK, attn);

    softmax_kernel<<<dim3(NZ * LL), dim3(256)>>>(attn);

    const int ctx_smem = 55296;
    cudaFuncSetAttribute(ctx_mma, cudaFuncAttributeMaxDynamicSharedMemorySize, ctx_smem);
    ctx_mma<<<dim3(LL / 128, NZ), dim3(512), ctx_smem>>>(attn, gVTH, gVTL, gCtx);

    const int out_smem = 34816;
    cudaFuncSetAttribute(out_mma, cudaFuncAttributeMaxDynamicSharedMemorySize, out_smem);
    out_mma<<<dim3(DM / 64, (BB * LL) / 128), dim3(256), out_smem>>>(gCtx, wo, out);
}

// round 12
// speedup vs baseline: 1.1561x; 1.0425x over previous
#include <cuda_runtime.h>
#include <cuda_bf16.h>
#include <cstdint>

#define BB 4
#define HH 16
#define LL 2048
#define DM 1024
#define DHEAD 64
#define NZ (BB * HH)

// Scratch (__device__ globals; allocation-free rule)
__device__ float g_Q[(size_t)NZ * LL * DHEAD];
__device__ float g_K[(size_t)NZ * LL * DHEAD];
__device__ float g_VT[(size_t)NZ * DHEAD * LL];   // V^T fp32 [z][e][kv]
__device__ float g_ctx[(size_t)BB * LL * (HH * DHEAD)];

// ===========================================================================
// tf32 mma.sync (m16n8k8) + bf16 mma.sync (m16n8k16) helpers
// ===========================================================================
__device__ __forceinline__ void mma_tf32(float* c,
                                         uint32_t a0, uint32_t a1, uint32_t a2, uint32_t a3,
                                         uint32_t b0, uint32_t b1)
{
    asm volatile(
        "mma.sync.aligned.m16n8k8.row.col.f32.tf32.tf32.f32 "
        "{%0,%1,%2,%3}, {%4,%5,%6,%7}, {%8,%9}, {%0,%1,%2,%3};"
        : "+f"(c[0]), "+f"(c[1]), "+f"(c[2]), "+f"(c[3])
        : "r"(a0), "r"(a1), "r"(a2), "r"(a3), "r"(b0), "r"(b1));
}
__device__ __forceinline__ uint32_t f2tf32(float x)
{
    uint32_t r;
    asm("cvt.rna.tf32.f32 %0, %1;" : "=r"(r) : "f"(x));
    return r;
}
__device__ __forceinline__ void mma_bf16(float* c,
                                         uint32_t a0, uint32_t a1, uint32_t a2, uint32_t a3,
                                         uint32_t b0, uint32_t b1)
{
    asm volatile(
        "mma.sync.aligned.m16n8k16.row.col.f32.bf16.bf16.f32 "
        "{%0,%1,%2,%3}, {%4,%5,%6,%7}, {%8,%9}, {%0,%1,%2,%3};"
        : "+f"(c[0]), "+f"(c[1]), "+f"(c[2]), "+f"(c[3])
        : "r"(a0), "r"(a1), "r"(a2), "r"(a3), "r"(b0), "r"(b1));
}
__device__ __forceinline__ void mma3(float* c,
                                     const uint32_t* ah, const uint32_t* al,
                                     const uint32_t* bh, const uint32_t* bl)
{
    mma_bf16(c, ah[0], ah[1], ah[2], ah[3], bh[0], bh[1]);
    mma_bf16(c, ah[0], ah[1], ah[2], ah[3], bl[0], bl[1]);
    mma_bf16(c, al[0], al[1], al[2], al[3], bh[0], bh[1]);
}
__device__ __forceinline__ void split_pair(float x, float y, uint32_t& h, uint32_t& l)
{
    __nv_bfloat16 hx = __float2bfloat16(x);
    __nv_bfloat16 hy = __float2bfloat16(y);
    __nv_bfloat162 hp = __halves2bfloat162(hx, hy);
    __nv_bfloat162 lp = __halves2bfloat162(__float2bfloat16(x - __bfloat162float(hx)),
                                           __float2bfloat16(y - __bfloat162float(hy)));
    h = *(uint32_t*)&hp;
    l = *(uint32_t*)&lp;
}
__device__ __forceinline__ void split_one(float x, __nv_bfloat16& h, __nv_bfloat16& l)
{
    h = __float2bfloat16(x);
    l = __float2bfloat16(x - __bfloat162float(h));
}

// ===========================================================================
// score_mma: S[z,i,j] = 0.125 * Q·K^T   (tf32)
// CTA 128x128, 512 threads / 16 warps (4x4), warp tile 32x32. 8 k8-steps.
// grid=(16 j, 16 i, 64 z), smem 69632 B
// ===========================================================================
__global__ __launch_bounds__(512) void score_mma(const float* __restrict__ Qp,
                                                 const float* __restrict__ Kp,
                                                 float* __restrict__ Sout)
{
    extern __shared__ char smraw[];
    uint32_t* Qs = (uint32_t*)smraw;        // [128][68]
    uint32_t* Ks = Qs + 128 * 68;           // [128][68]
    float* Ssm = (float*)smraw;             // epilogue reuse [128][132]

    const int tid = threadIdx.x, wid = tid >> 5, lane = tid & 31;
    const int wm = (wid >> 2) * 32, wn = (wid & 3) * 32;
    const int z = blockIdx.z, i0 = blockIdx.y * 128, j0 = blockIdx.x * 128;
    const float* Q = Qp + (size_t)z * LL * DHEAD;
    const float* K = Kp + (size_t)z * LL * DHEAD;

    #pragma unroll
    for (int t = 0; t < 4; t++) {
        int v = tid + t * 512;
        int r = v >> 4, c = (v & 15) * 4;
        float4 qv = *(const float4*)&Q[(size_t)(i0 + r) * DHEAD + c];
        Qs[r * 68 + c + 0] = f2tf32(qv.x); Qs[r * 68 + c + 1] = f2tf32(qv.y);
        Qs[r * 68 + c + 2] = f2tf32(qv.z); Qs[r * 68 + c + 3] = f2tf32(qv.w);
        float4 kv = *(const float4*)&K[(size_t)(j0 + r) * DHEAD + c];
        Ks[r * 68 + c + 0] = f2tf32(kv.x); Ks[r * 68 + c + 1] = f2tf32(kv.y);
        Ks[r * 68 + c + 2] = f2tf32(kv.z); Ks[r * 68 + c + 3] = f2tf32(kv.w);
    }
    __syncthreads();

    float acc[2][4][4] = {};
    const int fr = lane >> 2, fc = lane & 3;

    #pragma unroll
    for (int ks = 0; ks < 8; ks++) {
        const int k0 = ks * 8;
        uint32_t b0[4], b1[4];
        #pragma unroll
        for (int jn = 0; jn < 4; jn++) {
            int n = wn + jn * 8 + fr;
            b0[jn] = Ks[n * 68 + k0 + fc];
            b1[jn] = Ks[n * 68 + k0 + fc + 4];
        }
        #pragma unroll
        for (int im = 0; im < 2; im++) {
            int m = wm + im * 16 + fr;
            uint32_t a0 = Qs[m * 68 + k0 + fc];
            uint32_t a1 = Qs[(m + 8) * 68 + k0 + fc];
            uint32_t a2 = Qs[m * 68 + k0 + fc + 4];
            uint32_t a3 = Qs[(m + 8) * 68 + k0 + fc + 4];
            #pragma unroll
            for (int jn = 0; jn < 4; jn++)
                mma_tf32(acc[im][jn], a0, a1, a2, a3, b0[jn], b1[jn]);
        }
    }
    __syncthreads();

    const int qr = lane >> 2, qc = (lane & 3) * 2;
    #pragma unroll
    for (int im = 0; im < 2; im++) {
        int row = wm + im * 16 + qr;
        #pragma unroll
        for (int jn = 0; jn < 4; jn++) {
            int col = wn + jn * 8 + qc;
            *(float2*)&Ssm[row * 132 + col] =
                make_float2(acc[im][jn][0] * 0.125f, acc[im][jn][1] * 0.125f);
            *(float2*)&Ssm[(row + 8) * 132 + col] =
                make_float2(acc[im][jn][2] * 0.125f, acc[im][jn][3] * 0.125f);
        }
    }
    __syncthreads();

    float* S = Sout + (size_t)z * LL * LL;
    #pragma unroll
    for (int t = 0; t < 8; t++) {
        int v = tid + t * 512;
        int r = v >> 5, c = (v & 31) * 4;
        *(float4*)&S[(size_t)(i0 + r) * LL + j0 + c] = *(float4*)&Ssm[r * 132 + c];
    }
}

// ===========================================================================
// ctx_mma: C[z] = attn[z](2048x2048) @ V[z](2048x64)   (tf32)
// CTA 128x64, 512 threads / 16 warps (8x2), warp tile 16x32. kv chunks of 64.
// grid=(16 i, 64 z), smem 52224 B
// ===========================================================================
__global__ __launch_bounds__(512) void ctx_mma(const float* __restrict__ Sm,
                                               const float* __restrict__ VT,
                                               float* __restrict__ Ctx)
{
    extern __shared__ char smraw[];
    uint32_t* As = (uint32_t*)smraw;        // [128][68]
    uint32_t* Ts = As + 128 * 68;           // V^T chunk [64][68]
    float* Cs = (float*)smraw;              // epilogue reuse [128][68]

    const int tid = threadIdx.x, wid = tid >> 5, lane = tid & 31;
    const int wm = (wid >> 1) * 16, wn = (wid & 1) * 32;
    const int z = blockIdx.y, b = z >> 4, h = z & 15;
    const int i0 = blockIdx.x * 128;
    const float* A = Sm + (size_t)z * LL * LL;

    const int fr = lane >> 2, fc = lane & 3;
    float acc[4][4] = {};

    for (int c = 0; c < 32; c++) {
        const int kv0 = c * 64;
        #pragma unroll
        for (int t = 0; t < 4; t++) {
            int v = tid + t * 512;
            int r = v >> 4, cc = (v & 15) * 4;
            float4 av = *(const float4*)&A[(size_t)(i0 + r) * LL + kv0 + cc];
            As[r * 68 + cc + 0] = f2tf32(av.x); As[r * 68 + cc + 1] = f2tf32(av.y);
            As[r * 68 + cc + 2] = f2tf32(av.z); As[r * 68 + cc + 3] = f2tf32(av.w);
        }
        #pragma unroll
        for (int t = 0; t < 2; t++) {
            int v = tid + t * 512;
            int e = v >> 4, kp = (v & 15) * 4;
            float4 vv = *(const float4*)&VT[((size_t)z * DHEAD + e) * LL + kv0 + kp];
            Ts[e * 68 + kp + 0] = f2tf32(vv.x); Ts[e * 68 + kp + 1] = f2tf32(vv.y);
            Ts[e * 68 + kp + 2] = f2tf32(vv.z); Ts[e * 68 + kp + 3] = f2tf32(vv.w);
        }
        __syncthreads();

        #pragma unroll
        for (int ks = 0; ks < 8; ks++) {
            const int k0 = ks * 8;
            uint32_t b0[4], b1[4];
            #pragma unroll
            for (int jn = 0; jn < 4; jn++) {
                int n = wn + jn * 8 + fr;
                b0[jn] = Ts[n * 68 + k0 + fc];
                b1[jn] = Ts[n * 68 + k0 + fc + 4];
            }
            int m = wm + fr;
            uint32_t a0 = As[m * 68 + k0 + fc];
            uint32_t a1 = As[(m + 8) * 68 + k0 + fc];
            uint32_t a2 = As[m * 68 + k0 + fc + 4];
            uint32_t a3 = As[(m + 8) * 68 + k0 + fc + 4];
            #pragma unroll
            for (int jn = 0; jn < 4; jn++)
                mma_tf32(acc[jn], a0, a1, a2, a3, b0[jn], b1[jn]);
        }
        __syncthreads();
    }

    const int qr = lane >> 2, qc = (lane & 3) * 2;
    {
        int row = wm + qr;
        #pragma unroll
        for (int jn = 0; jn < 4; jn++) {
            int col = wn + jn * 8 + qc;
            *(float2*)&Cs[row * 68 + col] = make_float2(acc[jn][0], acc[jn][1]);
            *(float2*)&Cs[(row + 8) * 68 + col] = make_float2(acc[jn][2], acc[jn][3]);
        }
    }
    __syncthreads();
    #pragma unroll
    for (int t = 0; t < 4; t++) {
        int v = tid + t * 512;
        int r = v >> 4, cc = (v & 15) * 4;
        *(float4*)&Ctx[((size_t)b * LL + i0 + r) * (HH * DHEAD) + h * DHEAD + cc] =
            *(float4*)&Cs[r * 68 + cc];
    }
}

// ===========================================================================
// proj_mma: Out[b,h,s,e] = sum_d X[b,s,d] W[h,d,e]   (split-bf16, R10-exact)
// mode 0: float row-major Q/K.  mode 1: V^T fp32 [z][e][kv].
// ===========================================================================
__global__ __launch_bounds__(256) void proj_mma(const float* __restrict__ X,
                                                const float* __restrict__ W,
                                                float* __restrict__ OutF,
                                                float* __restrict__ OutT,
                                                int mode)
{
    extern __shared__ char smraw[];
    __nv_bfloat16* XH = (__nv_bfloat16*)smraw;     // [128][40]
    __nv_bfloat16* XL = XH + 128 * 40;
    __nv_bfloat16* TH = XL + 128 * 40;             // W^T [64 e][40]
    __nv_bfloat16* TL = TH + 64 * 40;
    float* Cs = (float*)smraw;                     // [128][68]

    const int tid = threadIdx.x, wid = tid >> 5, lane = tid & 31;
    const int wm = (wid >> 1) * 32, wn = (wid & 1) * 32;
    const int b = blockIdx.z, hh = blockIdx.y, i0 = blockIdx.x * 128;
    const int z = b * HH + hh;
    const float* A  = X + (size_t)b * LL * DM;
    const float* Bw = W + (size_t)hh * DM * DHEAD;

    const int qr = lane >> 2, qc = (lane & 3) * 2;
    float acc[2][4][4] = {};

    for (int c = 0; c < 32; c++) {
        const int k0g = c * 32;
        #pragma unroll
        for (int t = 0; t < 4; t++) {
            int v = tid + t * 256;
            int r = v >> 3, cc = (v & 7) * 4;
            float4 xv = *(const float4*)&A[(size_t)(i0 + r) * DM + k0g + cc];
            uint32_t h0, l0, h1, l1;
            split_pair(xv.x, xv.y, h0, l0);
            split_pair(xv.z, xv.w, h1, l1);
            *(uint32_t*)&XH[r * 40 + cc] = h0; *(uint32_t*)&XH[r * 40 + cc + 2] = h1;
            *(uint32_t*)&XL[r * 40 + cc] = l0; *(uint32_t*)&XL[r * 40 + cc + 2] = l1;
        }
        #pragma unroll
        for (int t = 0; t < 2; t++) {
            int v = tid + t * 256;
            int r = v >> 4, cc = (v & 15) * 4;
            float4 wv = *(const float4*)&Bw[(size_t)(k0g + r) * DHEAD + cc];
            float vals[4] = {wv.x, wv.y, wv.z, wv.w};
            #pragma unroll
            for (int jj = 0; jj < 4; jj++) {
                __nv_bfloat16 hh2, ll;
                split_one(vals[jj], hh2, ll);
                TH[(cc + jj) * 40 + r] = hh2;
                TL[(cc + jj) * 40 + r] = ll;
            }
        }
        __syncthreads();

        #pragma unroll
        for (int ks = 0; ks < 2; ks++) {
            const int k0 = ks * 16;
            uint32_t bh[4][2], bl[4][2];
            #pragma unroll
            for (int jn = 0; jn < 4; jn++) {
                int n = wn + jn * 8 + qr;
                bh[jn][0] = *(uint32_t*)&TH[n * 40 + k0 + qc];
                bh[jn][1] = *(uint32_t*)&TH[n * 40 + k0 + 8 + qc];
                bl[jn][0] = *(uint32_t*)&TL[n * 40 + k0 + qc];
                bl[jn][1] = *(uint32_t*)&TL[n * 40 + k0 + 8 + qc];
            }
            #pragma unroll
            for (int im = 0; im < 2; im++) {
                int m = wm + im * 16 + qr;
                uint32_t ah[4], al[4];
                ah[0] = *(uint32_t*)&XH[m * 40 + k0 + qc];
                ah[1] = *(uint32_t*)&XH[(m + 8) * 40 + k0 + qc];
                ah[2] = *(uint32_t*)&XH[m * 40 + k0 + 8 + qc];
                ah[3] = *(uint32_t*)&XH[(m + 8) * 40 + k0 + 8 + qc];
                al[0] = *(uint32_t*)&XL[m * 40 + k0 + qc];
                al[1] = *(uint32_t*)&XL[(m + 8) * 40 + k0 + qc];
                al[2] = *(uint32_t*)&XL[m * 40 + k0 + 8 + qc];
                al[3] = *(uint32_t*)&XL[(m + 8) * 40 + k0 + 8 + qc];
                #pragma unroll
                for (int jn = 0; jn < 4; jn++)
                    mma3(acc[im][jn], ah, al, bh[jn], bl[jn]);
            }
        }
        __syncthreads();
    }

    #pragma unroll
    for (int im = 0; im < 2; im++) {
        int row = wm + im * 16 + qr;
        #pragma unroll
        for (int jn = 0; jn < 4; jn++) {
            int col = wn + jn * 8 + qc;
            *(float2*)&Cs[row * 68 + col] = make_float2(acc[im][jn][0], acc[im][jn][1]);
            *(float2*)&Cs[(row + 8) * 68 + col] = make_float2(acc[im][jn][2], acc[im][jn][3]);
        }
    }
    __syncthreads();

    if (mode == 0) {
        float* Out = OutF + ((size_t)z * LL + i0) * DHEAD;
        #pragma unroll
        for (int t = 0; t < 8; t++) {
            int v = tid + t * 256;
            int r = v >> 4, cc = (v & 15) * 4;
            *(float4*)&Out[(size_t)r * DHEAD + cc] = *(float4*)&Cs[r * 68 + cc];
        }
    } else {
        // V^T fp32: [z][e][kv]
        #pragma unroll
        for (int t = 0; t < 32; t++) {
            int v = tid + t * 256;
            int e = v >> 7, row = v & 127;
            OutT[((size_t)z * DHEAD + e) * LL + i0 + row] = Cs[row * 68 + e];
        }
    }
}

// ===========================================================================
// out_mma: Out(8192x1024) = Ctx(8192x1024) @ Wo(1024x1024)   (split-bf16)
// ===========================================================================
__global__ __launch_bounds__(256) void out_mma(const float* __restrict__ Ctx,
                                               const float* __restrict__ Wo,
                                               float* __restrict__ Out)
{
    extern __shared__ char smraw[];
    __nv_bfloat16* XH = (__nv_bfloat16*)smraw;     // [128][40]
    __nv_bfloat16* XL = XH + 128 * 40;
    __nv_bfloat16* TH = XL + 128 * 40;             // Wo^T [64 n][40]
    __nv_bfloat16* TL = TH + 64 * 40;
    float* Cs = (float*)smraw;

    const int tid = threadIdx.x, wid = tid >> 5, lane = tid & 31;
    const int wm = (wid >> 1) * 32, wn = (wid & 1) * 32;
    const int i0 = blockIdx.y * 128, j0 = blockIdx.x * 64;
    const int NN = HH * DHEAD;

    const int qr = lane >> 2, qc = (lane & 3) * 2;
    float acc[2][4][4] = {};

    for (int c = 0; c < 32; c++) {
        const int k0g = c * 32;
        #pragma unroll
        for (int t = 0; t < 4; t++) {
            int v = tid + t * 256;
            int r = v >> 3, cc = (v & 7) * 4;
            float4 xv = *(const float4*)&Ctx[(size_t)(i0 + r) * NN + k0g + cc];
            uint32_t h0, l0, h1, l1;
            split_pair(xv.x, xv.y, h0, l0);
            split_pair(xv.z, xv.w, h1, l1);
            *(uint32_t*)&XH[r * 40 + cc] = h0; *(uint32_t*)&XH[r * 40 + cc + 2] = h1;
            *(uint32_t*)&XL[r * 40 + cc] = l0; *(uint32_t*)&XL[r * 40 + cc + 2] = l1;
        }
        #pragma unroll
        for (int t = 0; t < 2; t++) {
            int v = tid + t * 256;
            int r = v >> 4, cc = (v & 15) * 4;
            float4 wv = *(const float4*)&Wo[(size_t)(k0g + r) * DM + j0 + cc];
            float vals[4] = {wv.x, wv.y, wv.z, wv.w};
            #pragma unroll
            for (int jj = 0; jj < 4; jj++) {
                __nv_bfloat16 hh, ll;
                split_one(vals[jj], hh, ll);
                TH[(cc + jj) * 40 + r] = hh;
                TL[(cc + jj) * 40 + r] = ll;
            }
        }
        __syncthreads();

        #pragma unroll
        for (int ks = 0; ks < 2; ks++) {
            const int k0 = ks * 16;
            uint32_t bh[4][2], bl[4][2];
            #pragma unroll
            for (int jn = 0; jn < 4; jn++) {
                int n = wn + jn * 8 + qr;
                bh[jn][0] = *(uint32_t*)&TH[n * 40 + k0 + qc];
                bh[jn][1] = *(uint32_t*)&TH[n * 40 + k0 + 8 + qc];
                bl[jn][0] = *(uint32_t*)&TL[n * 40 + k0 + qc];
                bl[jn][1] = *(uint32_t*)&TL[n * 40 + k0 + 8 + qc];
            }
            #pragma unroll
            for (int im = 0; im < 2; im++) {
                int m = wm + im * 16 + qr;
                uint32_t ah[4], al[4];
                ah[0] = *(uint32_t*)&XH[m * 40 + k0 + qc];
                ah[1] = *(uint32_t*)&XH[(m + 8) * 40 + k0 + qc];
                ah[2] = *(uint32_t*)&XH[m * 40 + k0 + 8 + qc];
                ah[3] = *(uint32_t*)&XH[(m + 8) * 40 + k0 + 8 + qc];
                al[0] = *(uint32_t*)&XL[m * 40 + k0 + qc];
                al[1] = *(uint32_t*)&XL[(m + 8) * 40 + k0 + qc];
                al[2] = *(uint32_t*)&XL[m * 40 + k0 + 8 + qc];
                al[3] = *(uint32_t*)&XL[(m + 8) * 40 + k0 + 8 + qc];
                #pragma unroll
                for (int jn = 0; jn < 4; jn++)
                    mma3(acc[im][jn], ah, al, bh[jn], bl[jn]);
            }
        }
        __syncthreads();
    }

    #pragma unroll
    for (int im = 0; im < 2; im++) {
        int row = wm + im * 16 + qr;
        #pragma unroll
        for (int jn = 0; jn < 4; jn++) {
            int col = wn + jn * 8 + qc;
            *(float2*)&Cs[row * 68 + col] = make_float2(acc[im][jn][0], acc[im][jn][1]);
            *(float2*)&Cs[(row + 8) * 68 + col] = make_float2(acc[im][jn][2], acc[im][jn][3]);
        }
    }
    __syncthreads();
    #pragma unroll
    for (int t = 0; t < 8; t++) {
        int v = tid + t * 256;
        int r = v >> 4, cc = (v & 15) * 4;
        *(float4*)&Out[(size_t)(i0 + r) * DM + j0 + cc] = *(float4*)&Cs[r * 68 + cc];
    }
}

// ===========================================================================
// Row softmax, 2048 elems, in place. grid=(131072), block=256
// ===========================================================================
__global__ __launch_bounds__(256) void softmax_kernel(float* __restrict__ S)
{
    float4* p4 = (float4*)(S + (size_t)blockIdx.x * LL);
    const int tid = threadIdx.x;
    const int warp = tid >> 5, lane = tid & 31;
    __shared__ float red[8];

    float4 v0 = p4[tid], v1 = p4[tid + 256];
    float m = fmaxf(fmaxf(fmaxf(v0.x, v0.y), fmaxf(v0.z, v0.w)),
                    fmaxf(fmaxf(v1.x, v1.y), fmaxf(v1.z, v1.w)));
    #pragma unroll
    for (int o = 16; o > 0; o >>= 1) m = fmaxf(m, __shfl_xor_sync(0xffffffffu, m, o));
    if (lane == 0) red[warp] = m;
    __syncthreads();
    if (tid < 8) {
        float t = red[tid];
        #pragma unroll
        for (int o = 4; o > 0; o >>= 1) t = fmaxf(t, __shfl_xor_sync(0xffu, t, o));
        if (tid == 0) red[0] = t;
    }
    __syncthreads();
    m = red[0];
    __syncthreads();

    v0.x = __expf(v0.x - m); v0.y = __expf(v0.y - m);
    v0.z = __expf(v0.z - m); v0.w = __expf(v0.w - m);
    v1.x = __expf(v1.x - m); v1.y = __expf(v1.y - m);
    v1.z = __expf(v1.z - m); v1.w = __expf(v1.w - m);
    float s = v0.x + v0.y + v0.z + v0.w + v1.x + v1.y + v1.z + v1.w;
    #pragma unroll
    for (int o = 16; o > 0; o >>= 1) s += __shfl_xor_sync(0xffffffffu, s, o);
    if (lane == 0) red[warp] = s;
    __syncthreads();
    if (tid < 8) {
        float t = red[tid];
        #pragma unroll
        for (int o = 4; o > 0; o >>= 1) t += __shfl_xor_sync(0xffu, t, o);
        if (tid == 0) red[0] = t;
    }
    __syncthreads();
    float inv = 1.0f / red[0];

    v0.x *= inv; v0.y *= inv; v0.z *= inv; v0.w *= inv;
    v1.x *= inv; v1.y *= inv; v1.z *= inv; v1.w *= inv;
    p4[tid] = v0; p4[tid + 256] = v1;
}

// ===========================================================================
extern "C" void kernel_launch(void* const* d_in, const int* in_sizes, int n_in,
                              void* d_out, int out_size)
{
    const float* q  = (const float*)d_in[0];
    const float* k  = (const float*)d_in[1];
    const float* v  = (const float*)d_in[2];
    const float* wq = (const float*)d_in[3];
    const float* wk = (const float*)d_in[4];
    const float* wv = (const float*)d_in[5];
    const float* wo = (const float*)d_in[6];

    float* out = (float*)d_out;
    const size_t OUT_ELEMS = (size_t)BB * LL * DM;

    float *gQ, *gK, *gVT, *gCtx;
    cudaGetSymbolAddress((void**)&gQ, g_Q);
    cudaGetSymbolAddress((void**)&gK, g_K);
    cudaGetSymbolAddress((void**)&gVT, g_VT);
    cudaGetSymbolAddress((void**)&gCtx, g_ctx);

    float* attn = out + OUT_ELEMS;

    const int proj_smem = 34816;
    cudaFuncSetAttribute(proj_mma, cudaFuncAttributeMaxDynamicSharedMemorySize, proj_smem);
    proj_mma<<<dim3(LL / 128, HH, BB), dim3(256), proj_smem>>>(q, wq, gQ, nullptr, 0);
    proj_mma<<<dim3(LL / 128, HH, BB), dim3(256), proj_smem>>>(k, wk, gK, nullptr, 0);
    proj_mma<<<dim3(LL / 128, HH, BB), dim3(256), proj_smem>>>(v, wv, nullptr, gVT, 1);

    const int score_smem = 69632;
    cudaFuncSetAttribute(score_mma, cudaFuncAttributeMaxDynamicSharedMemorySize, score_smem);
    score_mma<<<dim3(LL / 128, LL / 128, NZ), dim3(512), score_smem>>>(gQ, gK, attn);

    softmax_kernel<<<dim3(NZ * LL), dim3(256)>>>(attn);

    const int ctx_smem = 52224;
    cudaFuncSetAttribute(ctx_mma, cudaFuncAttributeMaxDynamicSharedMemorySize, ctx_smem);
    ctx_mma<<<dim3(LL / 128, NZ), dim3(512), ctx_smem>>>(attn, gVT, gCtx);

    const int out_smem = 34816;
    cudaFuncSetAttribute(out_mma, cudaFuncAttributeMaxDynamicSharedMemorySize, out_smem);
    out_mma<<<dim3(DM / 64, (BB * LL) / 128), dim3(256), out_smem>>>(gCtx, wo, out);
}